// round 9
// baseline (speedup 1.0000x reference)
#include <cuda_runtime.h>

#define NA 1024
#define NC 6
#define HH 48
#define NB_BINS 36
#define K_SP 1728          // 36*48
#define CE 64
#define VFC 16
#define OUT_C 128          // 64 + 16 + 48
#define M_ROWS (NA * NC)   // 6144
#define MAXE 512           // max supported episode size

typedef unsigned long long u64;

// ---- packed f32x2 helpers (Blackwell FFMA2 pipe) --------------------------
__device__ __forceinline__ u64 pack2(float lo, float hi) {
    u64 r; asm("mov.b64 %0, {%1,%2};" : "=l"(r) : "f"(lo), "f"(hi)); return r;
}
__device__ __forceinline__ u64 fma2(u64 a, u64 b, u64 c) {
    u64 d; asm("fma.rn.f32x2 %0, %1, %2, %3;" : "=l"(d) : "l"(a), "l"(b), "l"(c));
    return d;
}
__device__ __forceinline__ float2 unpack2(u64 v) {
    float2 f; asm("mov.b64 {%0,%1}, %2;" : "=f"(f.x), "=f"(f.y) : "l"(v)); return f;
}

// hW[row=(b*NC+c), bin*48+n] = hidden[row,:] @ Ws[bin*48:(bin+1)*48, :]
__device__ float g_hw[M_ROWS * K_SP];

// ---------------------------------------------------------------------------
// Kernel P: hW precompute. grid (48, 36), block 256. 4 rows x 6 cols/thread,
// M-pair f32x2 packing: A pairs native from A^T smem (LDS.128 = 2 pairs),
// B splatted (b,b) at load. Inner k-iter: 4 LDS.128 + 12 FFMA2, zero MOVs.
// ---------------------------------------------------------------------------
#define PM 128
#define ASTRIDE (PM + 4)   // 132 (row starts stay 16B-aligned)

__global__ void __launch_bounds__(256) hw_kernel(
    const float* __restrict__ hidden,     // [M_ROWS, 48]
    const float* __restrict__ Ws)         // [1728, 48]
{
    __shared__ float Asm[HH][ASTRIDE];    // A^T : Asm[k][m]      25.3 KB
    __shared__ u64   Bs2[HH][HH];         // splatted (b,b)       18.4 KB

    const int m0  = blockIdx.x * PM;
    const int bin = blockIdx.y;
    const int tid = threadIdx.x;

    // load A transposed: 128 rows x 48 k  (1536 float4)
    for (int l = tid; l < (PM * HH) / 4; l += 256) {
        int m  = l / (HH / 4);
        int kq = (l % (HH / 4)) * 4;
        float4 v = *(const float4*)&hidden[(m0 + m) * HH + kq];
        Asm[kq + 0][m] = v.x;
        Asm[kq + 1][m] = v.y;
        Asm[kq + 2][m] = v.z;
        Asm[kq + 3][m] = v.w;
    }
    // load + splat B block: Ws rows [bin*48, bin*48+48)
    for (int l = tid; l < HH * HH; l += 256) {
        int i = l / HH, j = l % HH;
        float b = Ws[(bin * HH + i) * HH + j];
        Bs2[i][j] = pack2(b, b);
    }
    __syncthreads();

    const int ty = tid / 8;               // 32 groups: rows ty*4 .. ty*4+3
    const int tx = tid % 8;               // cols tx*6 .. tx*6+5

    u64 acc[2][6];                        // 2 row-pairs x 6 cols
#pragma unroll
    for (int p = 0; p < 2; p++)
#pragma unroll
        for (int j = 0; j < 6; j++) acc[p][j] = 0ull;

#pragma unroll 12
    for (int k = 0; k < HH; k++) {
        ulonglong2 a01 = *(const ulonglong2*)&Asm[k][ty * 4];     // (m0,m1),(m2,m3)
        ulonglong2 b01 = *(const ulonglong2*)&Bs2[k][tx * 6 + 0];
        ulonglong2 b23 = *(const ulonglong2*)&Bs2[k][tx * 6 + 2];
        ulonglong2 b45 = *(const ulonglong2*)&Bs2[k][tx * 6 + 4];
        u64 ap[2]  = { a01.x, a01.y };
        u64 bv[6]  = { b01.x, b01.y, b23.x, b23.y, b45.x, b45.y };
#pragma unroll
        for (int p = 0; p < 2; p++)
#pragma unroll
            for (int j = 0; j < 6; j++)
                acc[p][j] = fma2(ap[p], bv[j], acc[p][j]);
    }

#pragma unroll
    for (int p = 0; p < 2; p++) {
        int r0 = m0 + ty * 4 + 2 * p;
        float* d0 = &g_hw[r0 * K_SP + bin * HH + tx * 6];
        float* d1 = d0 + K_SP;
#pragma unroll
        for (int j = 0; j < 6; j++) {
            float2 v = unpack2(acc[p][j]);
            d0[j] = v.x;
            d1[j] = v.y;
        }
    }
}

// ---------------------------------------------------------------------------
// Kernel Q: gather (R7 skeleton) with (off, w) packed into one int2 so the
// hot loop is LDS.64 + IADD + LDG + FFMA.
// ---------------------------------------------------------------------------
__global__ void __launch_bounds__(192) gather_kernel(
    const float* __restrict__ position,   // [M_ROWS, 2]
    const int*   __restrict__ ntt,        // [nb]
    const float* __restrict__ scene,      // [M_ROWS, 64]
    const float* __restrict__ velocity,   // [M_ROWS, 2]
    const float* __restrict__ Wv,         // [2, 16]
    const float* __restrict__ bv,         // [16]
    const float* __restrict__ bs,         // [48]
    float* __restrict__ out,              // [M_ROWS, 128]
    int nb)
{
    const int row = blockIdx.x;           // a*NC + c
    const int a = row / NC;
    const int c = row % NC;
    const int tid = threadIdx.x;

    __shared__ int   s_bin[MAXE];
    __shared__ int2  s_ow[MAXE];          // (offset, weight-bits)
    __shared__ int   s_cnt[NB_BINS];
    __shared__ float s_inv[NB_BINS];
    __shared__ float s_red[4][HH];

    if (tid < NB_BINS) s_cnt[tid] = 0;

    // episode [start, end) containing agent a
    int start = 0, end = 0, cum = 0;
    for (int i = 0; i < nb; i++) {
        int s = ntt[i];
        if (a >= cum && a < cum + s) { start = cum; end = cum + s; }
        cum += s;
    }
    int esz = end - start;
    if (esz > MAXE) esz = MAXE;

    const float px = position[row * 2 + 0];
    const float py = position[row * 2 + 1];
    const float rlogf = 0.34657359027997264f;   // log(RMAX/RMIN)/NUM_RINGS
    const float PIf   = 3.14159265358979323846f;

    __syncthreads();

    // pass 1: bins + counts
    for (int b = tid; b < esz; b += 192) {
        int brow = (start + b) * NC + c;
        float xd = px - position[brow * 2 + 0];
        float yd = py - position[brow * 2 + 1];
        float dist = sqrtf(xd * xd + yd * yd);
        int ring = (int)floorf(logf(dist / 0.5f + 1e-6f) / rlogf);
        int bin = -1;
        if (ring >= 0 && ring < 6) {
            float theta = atan2f(yd, xd);
            int wedge = (int)floorf((theta + PIf - 1e-6f) / PIf / 2.0f * 6.0f);
            bin = ring * 6 + wedge;
            if (bin < 0 || bin >= NB_BINS) bin = -1;
        }
        s_bin[b] = bin;
        if (bin >= 0) atomicAdd(&s_cnt[bin], 1);
    }
    __syncthreads();
    if (tid < NB_BINS) s_inv[tid] = 1.0f / (float)max(s_cnt[tid], 1);
    __syncthreads();
    // pass 1b: packed per-agent descriptor
    for (int b = tid; b < esz; b += 192) {
        int bin = s_bin[b];
        int off = ((start + b) * NC + c) * K_SP + max(bin, 0) * HH;
        float w = (bin >= 0) ? s_inv[bin] : 0.0f;
        s_ow[b] = make_int2(off, __float_as_int(w));
    }
    __syncthreads();

    // pass 2: gather-sum (4 groups x 48 cols)
    const int bq = tid / HH;              // 0..3
    const int n  = tid % HH;
    float acc = 0.0f;
    if (bq < 4) {
        for (int b = bq; b < esz; b += 4) {
            int2 q = s_ow[b];
            acc += g_hw[q.x + n] * __int_as_float(q.y);
        }
        s_red[bq][n] = acc;
    }

    // fused concat while the reduction lands: scene cols [0,64)
    for (int l = tid; l < CE; l += 192)
        out[row * OUT_C + l] = scene[row * CE + l];
    // velocity encoder cols [64,80)
    if (tid >= HH && tid < HH + VFC) {
        int o = tid - HH;
        float v = velocity[row * 2 + 0] * Wv[o]
                + velocity[row * 2 + 1] * Wv[VFC + o] + bv[o];
        out[row * OUT_C + CE + o] = fmaxf(v, 0.0f);
    }
    __syncthreads();

    // final reduce + bias + relu -> cols [80,128)
    if (tid < HH) {
        float t = s_red[0][tid] + s_red[1][tid] + s_red[2][tid] + s_red[3][tid];
        out[row * OUT_C + CE + VFC + tid] = fmaxf(t + bs[tid], 0.0f);
    }
}

// ---------------------------------------------------------------------------
extern "C" void kernel_launch(void* const* d_in, const int* in_sizes, int n_in,
                              void* d_out, int out_size)
{
    const float* hidden   = (const float*)d_in[0];
    const float* velocity = (const float*)d_in[1];
    const float* position = (const float*)d_in[2];
    const float* scene    = (const float*)d_in[3];
    const int*   ntt      = (const int*)d_in[4];
    const float* Wv       = (const float*)d_in[5];
    const float* bv       = (const float*)d_in[6];
    const float* Ws       = (const float*)d_in[7];
    const float* bs       = (const float*)d_in[8];
    float* out = (float*)d_out;
    int nb = in_sizes[4];

    hw_kernel<<<dim3(M_ROWS / PM, NB_BINS), 256>>>(hidden, Ws);
    gather_kernel<<<M_ROWS, 192>>>(position, ntt, scene, velocity,
                                   Wv, bv, bs, out, nb);
}

// round 10
// speedup vs baseline: 1.6414x; 1.6414x over previous
#include <cuda_runtime.h>

#define NA 1024
#define NC 6
#define HH 48
#define NB_BINS 36
#define K_SP 1728          // 36*48
#define CE 64
#define VFC 16
#define OUT_C 128          // 64 + 16 + 48
#define M_ROWS (NA * NC)   // 6144
#define MAXE 512           // max supported episode size

typedef unsigned long long u64;

// ---- packed f32x2 helpers (Blackwell FFMA2 pipe) --------------------------
__device__ __forceinline__ u64 pack2(float lo, float hi) {
    u64 r; asm("mov.b64 %0, {%1,%2};" : "=l"(r) : "f"(lo), "f"(hi)); return r;
}
__device__ __forceinline__ u64 fma2(u64 a, u64 b, u64 c) {
    u64 d; asm("fma.rn.f32x2 %0, %1, %2, %3;" : "=l"(d) : "l"(a), "l"(b), "l"(c));
    return d;
}
__device__ __forceinline__ float2 unpack2(u64 v) {
    float2 f; asm("mov.b64 {%0,%1}, %2;" : "=f"(f.x), "=f"(f.y) : "l"(v)); return f;
}

// ---- device scratch -------------------------------------------------------
__device__ float g_hw[M_ROWS * K_SP];      // hW[row, bin*48+n]
__device__ int2  g_desc[M_ROWS * MAXE];    // per (row, agent): (offset, w bits)
__device__ int   g_esz[M_ROWS];            // episode size per row

// ---------------------------------------------------------------------------
// Kernel 1 (combined): blocks [0, 1728) = hW GEMM tiles (exact R5/R7 hot
// loop); blocks [1728, 1728+1536) = binning for 4 rows each (trig + counts
// + descriptors). MUFU/ALU bin blocks overlap FFMA2 GEMM blocks.
// ---------------------------------------------------------------------------
#define PM 128
#define ASTRIDE (PM + 4)       // 132
#define NBLK_HW (M_ROWS / PM * NB_BINS)   // 48*36 = 1728
#define ROWS_PER_BINBLK 4
#define NBLK_BIN (M_ROWS / ROWS_PER_BINBLK)  // 1536
#define HW_SMEM_BYTES (HH * ASTRIDE * 4 + HH * HH * 4)   // 34560

__global__ void __launch_bounds__(256) hw_bin_kernel(
    const float* __restrict__ hidden,     // [M_ROWS, 48]
    const float* __restrict__ Ws,         // [1728, 48]
    const float* __restrict__ position,   // [M_ROWS, 2]
    const int*   __restrict__ ntt,        // [nb]
    int nb)
{
    __shared__ __align__(16) char sraw[HW_SMEM_BYTES];
    const int tid = threadIdx.x;

    if (blockIdx.x < NBLK_HW) {
        // ----------------- hW GEMM role (exact R5/R7 body) -----------------
        float (*Asm)[ASTRIDE] = (float(*)[ASTRIDE])sraw;
        float (*Bsm)[HH]      = (float(*)[HH])(sraw + HH * ASTRIDE * 4);

        const int m0  = (blockIdx.x % (M_ROWS / PM)) * PM;
        const int bin = blockIdx.x / (M_ROWS / PM);

        for (int l = tid; l < (PM * HH) / 4; l += 256) {
            int m  = l / (HH / 4);
            int kq = (l % (HH / 4)) * 4;
            float4 v = *(const float4*)&hidden[(m0 + m) * HH + kq];
            Asm[kq + 0][m] = v.x;
            Asm[kq + 1][m] = v.y;
            Asm[kq + 2][m] = v.z;
            Asm[kq + 3][m] = v.w;
        }
        for (int l = tid; l < (HH * HH) / 4; l += 256) {
            int i = l / (HH / 4);
            int j = (l % (HH / 4)) * 4;
            *(float4*)&Bsm[i][j] = *(const float4*)&Ws[(bin * HH + i) * HH + j];
        }
        __syncthreads();

        const int ty = tid / 8;           // rows ty*4 .. ty*4+3
        const int tx = tid % 8;           // col pairs at tx*6 + {0,2,4}

        u64 acc[4][3];
#pragma unroll
        for (int r = 0; r < 4; r++)
#pragma unroll
            for (int p = 0; p < 3; p++) acc[r][p] = pack2(0.0f, 0.0f);

#pragma unroll 12
        for (int k = 0; k < HH; k++) {
            float4 a = *(const float4*)&Asm[k][ty * 4];
            u64 b0 = *(const u64*)&Bsm[k][tx * 6 + 0];
            u64 b1 = *(const u64*)&Bsm[k][tx * 6 + 2];
            u64 b2 = *(const u64*)&Bsm[k][tx * 6 + 4];
            u64 ad[4] = { pack2(a.x, a.x), pack2(a.y, a.y),
                          pack2(a.z, a.z), pack2(a.w, a.w) };
#pragma unroll
            for (int r = 0; r < 4; r++) {
                acc[r][0] = fma2(ad[r], b0, acc[r][0]);
                acc[r][1] = fma2(ad[r], b1, acc[r][1]);
                acc[r][2] = fma2(ad[r], b2, acc[r][2]);
            }
        }

#pragma unroll
        for (int r = 0; r < 4; r++) {
            int row = m0 + ty * 4 + r;
            float2* dst = (float2*)&g_hw[row * K_SP + bin * HH + tx * 6];
            dst[0] = unpack2(acc[r][0]);
            dst[1] = unpack2(acc[r][1]);
            dst[2] = unpack2(acc[r][2]);
        }
    } else {
        // ----------------- binning role: 4 rows per block ------------------
        int*   s_bin = (int*)sraw;                         // [4][MAXE]
        int*   s_cnt = (int*)(sraw + 4 * MAXE * 4);        // [4][36]
        float* s_inv = (float*)(sraw + 4 * MAXE * 4 + 4 * NB_BINS * 4);

        const int base = (blockIdx.x - NBLK_HW) * ROWS_PER_BINBLK;
        const int sub  = tid / 64;        // 0..3
        const int lane = tid % 64;
        const int row  = base + sub;
        const int a = row / NC;
        const int c = row % NC;

        if (lane < NB_BINS) s_cnt[sub * NB_BINS + lane] = 0;

        int start = 0, end = 0, cum = 0;
        for (int i = 0; i < nb; i++) {
            int s = ntt[i];
            if (a >= cum && a < cum + s) { start = cum; end = cum + s; }
            cum += s;
        }
        int esz = end - start;
        if (esz > MAXE) esz = MAXE;

        const float px = position[row * 2 + 0];
        const float py = position[row * 2 + 1];
        const float rlogf = 0.34657359027997264f;
        const float PIf   = 3.14159265358979323846f;

        __syncthreads();

        for (int b = lane; b < esz; b += 64) {
            int brow = (start + b) * NC + c;
            float xd = px - position[brow * 2 + 0];
            float yd = py - position[brow * 2 + 1];
            float dist = sqrtf(xd * xd + yd * yd);
            int ring = (int)floorf(logf(dist / 0.5f + 1e-6f) / rlogf);
            int bin = -1;
            if (ring >= 0 && ring < 6) {
                float theta = atan2f(yd, xd);
                int wedge = (int)floorf((theta + PIf - 1e-6f) / PIf / 2.0f * 6.0f);
                bin = ring * 6 + wedge;
                if (bin < 0 || bin >= NB_BINS) bin = -1;
            }
            s_bin[sub * MAXE + b] = bin;
            if (bin >= 0) atomicAdd(&s_cnt[sub * NB_BINS + bin], 1);
        }
        __syncthreads();
        if (lane < NB_BINS)
            s_inv[sub * NB_BINS + lane] =
                1.0f / (float)max(s_cnt[sub * NB_BINS + lane], 1);
        __syncthreads();

        for (int b = lane; b < esz; b += 64) {
            int bin = s_bin[sub * MAXE + b];
            int off = ((start + b) * NC + c) * K_SP + max(bin, 0) * HH;
            float w = (bin >= 0) ? s_inv[sub * NB_BINS + bin] : 0.0f;
            g_desc[row * MAXE + b] = make_int2(off, __float_as_int(w));
        }
        if (lane == 0) g_esz[row] = esz;
    }
}

// ---------------------------------------------------------------------------
// Kernel 2: slim gather — load descriptors, sum, bias+relu, fused concat.
// (R7 pass-2 hot loop verbatim.)
// ---------------------------------------------------------------------------
__global__ void __launch_bounds__(192) gather_kernel(
    const float* __restrict__ scene,      // [M_ROWS, 64]
    const float* __restrict__ velocity,   // [M_ROWS, 2]
    const float* __restrict__ Wv,         // [2, 16]
    const float* __restrict__ bv,         // [16]
    const float* __restrict__ bs,         // [48]
    float* __restrict__ out)              // [M_ROWS, 128]
{
    const int row = blockIdx.x;
    const int tid = threadIdx.x;

    __shared__ int2  s_ow[MAXE];
    __shared__ float s_red[4][HH];

    const int esz = g_esz[row];
    for (int l = tid; l < esz; l += 192)
        s_ow[l] = g_desc[row * MAXE + l];

    // fused concat (no dependency on descriptors): scene cols [0,64)
    for (int l = tid; l < CE; l += 192)
        out[row * OUT_C + l] = scene[row * CE + l];
    // velocity encoder cols [64,80)
    if (tid >= HH && tid < HH + VFC) {
        int o = tid - HH;
        float v = velocity[row * 2 + 0] * Wv[o]
                + velocity[row * 2 + 1] * Wv[VFC + o] + bv[o];
        out[row * OUT_C + CE + o] = fmaxf(v, 0.0f);
    }
    __syncthreads();

    // gather-sum (4 groups x 48 cols) — R7 hot loop
    const int bq = tid / HH;              // 0..3
    const int n  = tid % HH;
    float acc = 0.0f;
    if (bq < 4) {
        for (int b = bq; b < esz; b += 4) {
            int2 q = s_ow[b];
            acc += g_hw[q.x + n] * __int_as_float(q.y);
        }
        s_red[bq][n] = acc;
    }
    __syncthreads();

    // final reduce + bias + relu -> cols [80,128)
    if (tid < HH) {
        float t = s_red[0][tid] + s_red[1][tid] + s_red[2][tid] + s_red[3][tid];
        out[row * OUT_C + CE + VFC + tid] = fmaxf(t + bs[tid], 0.0f);
    }
}

// ---------------------------------------------------------------------------
extern "C" void kernel_launch(void* const* d_in, const int* in_sizes, int n_in,
                              void* d_out, int out_size)
{
    const float* hidden   = (const float*)d_in[0];
    const float* velocity = (const float*)d_in[1];
    const float* position = (const float*)d_in[2];
    const float* scene    = (const float*)d_in[3];
    const int*   ntt      = (const int*)d_in[4];
    const float* Wv       = (const float*)d_in[5];
    const float* bv       = (const float*)d_in[6];
    const float* Ws       = (const float*)d_in[7];
    const float* bs       = (const float*)d_in[8];
    float* out = (float*)d_out;
    int nb = in_sizes[4];

    hw_bin_kernel<<<NBLK_HW + NBLK_BIN, 256>>>(hidden, Ws, position, ntt, nb);
    gather_kernel<<<M_ROWS, 192>>>(scene, velocity, Wv, bv, bs, out);
}